// round 8
// baseline (speedup 1.0000x reference)
#include <cuda_runtime.h>
#include <math.h>

#define BB  64
#define AA  16
#define CC  512
#define HH  30
#define WW  40
#define HWW 1200
#define EE  256
#define PP  512

#define OFF_Z  0
#define OFF_MU 76864
#define OFF_S2 76928
#define OFF_AX 76992
#define OFF_X  153792

#define NZ 10

typedef unsigned long long ull;

#define FMA_F32X2(d, a, b, c) \
    asm("fma.rn.f32x2 %0, %1, %2, %3;" : "=l"(d) : "l"(a), "l"(b), "l"(c))
#define PACK_DUP_F32X2(out, v) \
    asm("mov.b64 %0, {%1, %1};" : "=l"(out) : "f"(v))
#define UNPACK_F32X2(lo, hi, in) \
    asm("mov.b64 {%0, %1}, %2;" : "=f"(lo), "=f"(hi) : "l"(in))

// scratch: every element written each launch before being read (no zeroing needed)
__device__ float g_mean[BB * CC];
__device__ float g_y[BB * AA];
__device__ float g_t1p[8][BB * 48];
__device__ float g_scorep[8][BB * AA];
__device__ float g_aggrp[NZ][BB * AA * CC];

// stream + events created once at library load (host-side resources only)
static cudaStream_t g_s1;
static cudaEvent_t g_evFork, g_evJoin;
namespace {
struct InitStreams {
    InitStreams() {
        cudaStreamCreateWithFlags(&g_s1, cudaStreamNonBlocking);
        cudaEventCreateWithFlags(&g_evFork, cudaEventDisableTiming);
        cudaEventCreateWithFlags(&g_evJoin, cudaEventDisableTiming);
    }
};
InitStreams g_initStreams;
}

// ---------------------------------------------------------------------------
// x[b,a,hw] = relu(w_sal3[a,:] . F[b,:,hw] + b_sal3[a])
// grid (64, 5), block 128. Thread computes 2 hw (t, t+128) x 16 a.
// f32x2 accumulators over a-pairs; weight LDS amortized over 2 hw.
__global__ void __launch_bounds__(128) k_x(const float* __restrict__ F,
                                           const float* __restrict__ w3,
                                           const float* __restrict__ b3,
                                           float* __restrict__ out) {
    __shared__ float ws[CC * AA];  // transposed [c][a] -> natural a-pairs
    int b = blockIdx.x, tid = threadIdx.x;
    for (int i = tid; i < CC * AA; i += 128)
        ws[i] = w3[(i & 15) * CC + (i >> 4)];
    __syncthreads();

    int hw0 = blockIdx.y * 256 + tid;
    int hw1 = hw0 + 128;
    bool v0 = hw0 < HWW, v1 = hw1 < HWW;
    const float* Fb0 = F + (size_t)b * CC * HWW + (v0 ? hw0 : 0);
    const float* Fb1 = F + (size_t)b * CC * HWW + (v1 ? hw1 : 0);

    ull acc0[8], acc1[8];
    #pragma unroll
    for (int j = 0; j < 8; j++) { acc0[j] = 0ULL; acc1[j] = 0ULL; }

    #pragma unroll 4
    for (int c = 0; c < CC; c++) {
        float f0 = Fb0[c * HWW];
        float f1 = Fb1[c * HWW];
        ull f20, f21;
        PACK_DUP_F32X2(f20, f0);
        PACK_DUP_F32X2(f21, f1);
        const ulonglong2* wp = (const ulonglong2*)(ws + c * 16);
        ulonglong2 wA = wp[0];   // (a0,a1),(a2,a3)
        ulonglong2 wB = wp[1];   // (a4,a5),(a6,a7)
        ulonglong2 wC = wp[2];
        ulonglong2 wD = wp[3];
        FMA_F32X2(acc0[0], f20, wA.x, acc0[0]);
        FMA_F32X2(acc0[1], f20, wA.y, acc0[1]);
        FMA_F32X2(acc0[2], f20, wB.x, acc0[2]);
        FMA_F32X2(acc0[3], f20, wB.y, acc0[3]);
        FMA_F32X2(acc0[4], f20, wC.x, acc0[4]);
        FMA_F32X2(acc0[5], f20, wC.y, acc0[5]);
        FMA_F32X2(acc0[6], f20, wD.x, acc0[6]);
        FMA_F32X2(acc0[7], f20, wD.y, acc0[7]);
        FMA_F32X2(acc1[0], f21, wA.x, acc1[0]);
        FMA_F32X2(acc1[1], f21, wA.y, acc1[1]);
        FMA_F32X2(acc1[2], f21, wB.x, acc1[2]);
        FMA_F32X2(acc1[3], f21, wB.y, acc1[3]);
        FMA_F32X2(acc1[4], f21, wC.x, acc1[4]);
        FMA_F32X2(acc1[5], f21, wC.y, acc1[5]);
        FMA_F32X2(acc1[6], f21, wD.x, acc1[6]);
        FMA_F32X2(acc1[7], f21, wD.y, acc1[7]);
    }

    float* X = out + OFF_X + (size_t)b * AA * HWW;
    #pragma unroll
    for (int j = 0; j < 8; j++) {
        float lo0, hi0, lo1, hi1;
        UNPACK_F32X2(lo0, hi0, acc0[j]);
        UNPACK_F32X2(lo1, hi1, acc1[j]);
        float ba = b3[2 * j + 0], bb = b3[2 * j + 1];
        if (v0) {
            X[(2 * j + 0) * HWW + hw0] = fmaxf(lo0 + ba, 0.f);
            X[(2 * j + 1) * HWW + hw0] = fmaxf(hi0 + bb, 0.f);
        }
        if (v1) {
            X[(2 * j + 0) * HWW + hw1] = fmaxf(lo1 + ba, 0.f);
            X[(2 * j + 1) * HWW + hw1] = fmaxf(hi1 + bb, 0.f);
        }
    }
}

// ---------------------------------------------------------------------------
// Fused drt1 conv partials + per-channel mean of F.
// grid (64, 4), block 384; yoff selects half of the 8 channel-chunks.
__global__ void __launch_bounds__(384) k_drt1f(const float* __restrict__ F,
                                               const float* __restrict__ w1,
                                               int yoff) {
    __shared__ float ch[2][HWW];
    __shared__ float wsh[64 * 49];
    __shared__ float csum[2][12];
    __shared__ float pos_acc[336];

    int chunkid = blockIdx.y + yoff;
    int b = blockIdx.x, c0 = chunkid * 64;
    int tid = threadIdx.x;
    int wid = tid >> 5, lane = tid & 31;

    for (int i = tid; i < 64 * 49; i += 384) wsh[i] = w1[c0 * 49 + i];

    int pos = tid / 7, kh = tid - pos * 7;
    bool active = tid < 336;
    int oh = pos >> 3, ow = pos & 7;
    int ih = oh * 5 - 2 + kh;
    int iw0 = ow * 5 - 2;
    bool ihok = active && ih >= 0;

    const float* Fb = F + ((size_t)b * CC + c0) * HWW;

    {
        float ps = 0.f;
        if (tid < 300) {
            float4 v = ((const float4*)Fb)[tid];
            ((float4*)ch[0])[tid] = v;
            ps = v.x + v.y + v.z + v.w;
        }
        #pragma unroll
        for (int o = 16; o; o >>= 1) ps += __shfl_xor_sync(0xFFFFFFFFu, ps, o);
        if (!lane) csum[0][wid] = ps;
    }
    __syncthreads();

    float acc = 0.f;
    for (int c = 0; c < 64; c++) {
        int cur = c & 1;
        if (c < 63) {
            float ps = 0.f;
            if (tid < 300) {
                float4 v = ((const float4*)(Fb + (size_t)(c + 1) * HWW))[tid];
                ((float4*)ch[cur ^ 1])[tid] = v;
                ps = v.x + v.y + v.z + v.w;
            }
            #pragma unroll
            for (int o = 16; o; o >>= 1) ps += __shfl_xor_sync(0xFFFFFFFFu, ps, o);
            if (!lane) csum[cur ^ 1][wid] = ps;
        }
        if (tid == 0) {
            float m = 0.f;
            #pragma unroll
            for (int w = 0; w < 12; w++) m += csum[cur][w];
            g_mean[b * CC + c0 + c] = m * (1.f / HWW);
        }
        if (ihok) {
            const float* row = ch[cur] + ih * WW;
            const float* wr = wsh + c * 49 + kh * 7;
            #pragma unroll
            for (int kw = 0; kw < 7; kw++) {
                int iw = iw0 + kw;
                if (iw >= 0) acc += row[iw] * wr[kw];
            }
        }
        __syncthreads();
    }

    if (active) pos_acc[tid] = acc;
    __syncthreads();
    if (active && kh == 0) {
        float s = pos_acc[tid] + pos_acc[tid + 1] + pos_acc[tid + 2]
                + pos_acc[tid + 3] + pos_acc[tid + 4] + pos_acc[tid + 5]
                + pos_acc[tid + 6];
        g_t1p[chunkid][b * 48 + pos] = s;
    }
}

// ---------------------------------------------------------------------------
// merged y + drt2.  grid 64, block 512
__global__ void __launch_bounds__(512) k_ydrt2(
    const float* __restrict__ w2, const float* __restrict__ b2,
    const float* __restrict__ wd2, const float* __restrict__ bd2,
    const float* __restrict__ bd1, float* __restrict__ out) {
    __shared__ float t1s[48];
    int b = blockIdx.x, tid = threadIdx.x;
    int a = tid >> 5, lane = tid & 31;

    if (tid < 48) {
        float t = 0.f;
        #pragma unroll
        for (int j = 0; j < 8; j++) t += g_t1p[j][b * 48 + tid];
        t1s[tid] = fmaxf(t + bd1[0], 0.f);
    }

    const float4* m4 = (const float4*)(g_mean + b * CC);
    const float4* w4 = (const float4*)(w2 + a * CC);
    float s = 0.f;
    #pragma unroll
    for (int i = 0; i < 4; i++) {
        float4 mv = m4[lane + 32 * i];
        float4 wv = w4[lane + 32 * i];
        s += mv.x * wv.x + mv.y * wv.y + mv.z * wv.z + mv.w * wv.w;
    }
    #pragma unroll
    for (int o = 16; o; o >>= 1) s += __shfl_xor_sync(0xFFFFFFFFu, s, o);
    if (!lane) g_y[b * AA + a] = s + b2[a];

    __syncthreads();
    if (tid < 64) {
        int o = tid >> 5;
        float s2 = 0.f;
        for (int i = lane; i < 48; i += 32) s2 += t1s[i] * wd2[o * 48 + i];
        #pragma unroll
        for (int sh = 16; sh; sh >>= 1) s2 += __shfl_xor_sync(0xFFFFFFFFu, s2, sh);
        if (!lane) {
            float v = s2 + bd2[o];
            if (o == 0) out[OFF_MU + b] = v;
            else        out[OFF_S2 + b] = expf(v);
        }
    }
}

// ---------------------------------------------------------------------------
// aggr partial v3 (R6 scalar version): grid (64, NZ), block 256.
#define ACH 20
__global__ void __launch_bounds__(256) k_aggr(const float* __restrict__ Eenc,
                                              const float* __restrict__ out) {
    __shared__ float Esh[ACH * 512];     // [k][c]
    __shared__ float Xsh[ACH * 16];      // [k][a]
    int b = blockIdx.x;
    int z = blockIdx.y;
    int tid = threadIdx.x;
    int tc = tid & 63;
    int ta = tid >> 6;

    const float* Eb = Eenc + (size_t)b * CC * HWW;
    const float* Xb = out + OFF_X + (size_t)b * AA * HWW;

    float acc[4][8];
    #pragma unroll
    for (int i = 0; i < 4; i++)
        #pragma unroll
        for (int j = 0; j < 8; j++) acc[i][j] = 0.f;

    int hwbase = z * 120;
    for (int chk = 0; chk < 6; chk++) {
        int k0 = hwbase + chk * ACH;
        #pragma unroll
        for (int r = 0; r < 2; r++) {
            int c = tid + r * 256;
            const float4* Er = (const float4*)(Eb + (size_t)c * HWW + k0);
            #pragma unroll
            for (int q = 0; q < 5; q++) {
                float4 v = Er[q];
                Esh[(q * 4 + 0) * 512 + c] = v.x;
                Esh[(q * 4 + 1) * 512 + c] = v.y;
                Esh[(q * 4 + 2) * 512 + c] = v.z;
                Esh[(q * 4 + 3) * 512 + c] = v.w;
            }
        }
        if (tid < 80) {
            int aa = tid / 5, q = tid % 5;
            float4 v = *(const float4*)(Xb + aa * HWW + k0 + q * 4);
            Xsh[(q * 4 + 0) * 16 + aa] = v.x;
            Xsh[(q * 4 + 1) * 16 + aa] = v.y;
            Xsh[(q * 4 + 2) * 16 + aa] = v.z;
            Xsh[(q * 4 + 3) * 16 + aa] = v.w;
        }
        __syncthreads();
        #pragma unroll
        for (int k = 0; k < ACH; k++) {
            float4 e0 = *(const float4*)(Esh + k * 512 + tc * 4);
            float4 e1 = *(const float4*)(Esh + k * 512 + 256 + tc * 4);
            float4 xv = *(const float4*)(Xsh + k * 16 + ta * 4);
            float ev[8] = {e0.x, e0.y, e0.z, e0.w, e1.x, e1.y, e1.z, e1.w};
            float xa[4] = {xv.x, xv.y, xv.z, xv.w};
            #pragma unroll
            for (int i = 0; i < 4; i++)
                #pragma unroll
                for (int j = 0; j < 8; j++)
                    acc[i][j] += xa[i] * ev[j];
        }
        __syncthreads();
    }

    float* dst = g_aggrp[z] + (size_t)b * AA * CC;
    #pragma unroll
    for (int i = 0; i < 4; i++) {
        int a = ta * 4 + i;
        float4 s0, s1;
        s0.x = acc[i][0] * (1.f / HWW); s0.y = acc[i][1] * (1.f / HWW);
        s0.z = acc[i][2] * (1.f / HWW); s0.w = acc[i][3] * (1.f / HWW);
        s1.x = acc[i][4] * (1.f / HWW); s1.y = acc[i][5] * (1.f / HWW);
        s1.z = acc[i][6] * (1.f / HWW); s1.w = acc[i][7] * (1.f / HWW);
        *(float4*)(dst + a * CC + tc * 4) = s0;
        *(float4*)(dst + a * CC + 256 + tc * 4) = s1;
    }
}

// ---------------------------------------------------------------------------
// partial attention scores: grid (64, 8), block 256, 64 p's per block
__global__ void __launch_bounds__(256) k_score(
    const float* __restrict__ subj, const float* __restrict__ wps,
    const float* __restrict__ bps, const float* __restrict__ wpf,
    const float* __restrict__ bpf, const float* __restrict__ watt) {
    __shared__ float ssub[EE];
    __shared__ float ps[64];
    __shared__ float agg[AA * CC];
    __shared__ float scw[8][16];
    int b = blockIdx.x, p0 = blockIdx.y * 64;
    int tid = threadIdx.x;
    int wid = tid >> 5, lane = tid & 31;

    for (int i = tid; i < EE; i += 256) ssub[i] = subj[b * EE + i];
    for (int i = tid; i < AA * CC; i += 256) {
        float v = 0.f;
        #pragma unroll
        for (int z = 0; z < NZ; z++) v += g_aggrp[z][(size_t)b * AA * CC + i];
        agg[i] = v;
    }
    __syncthreads();

    for (int pi = wid; pi < 64; pi += 8) {
        int p = p0 + pi;
        const float4* w4 = (const float4*)(wps + p * EE);
        const float4* s4 = (const float4*)ssub;
        float s = 0.f;
        #pragma unroll
        for (int i = 0; i < 2; i++) {
            float4 wv = w4[lane + 32 * i], sv = s4[lane + 32 * i];
            s += wv.x * sv.x + wv.y * sv.y + wv.z * sv.z + wv.w * sv.w;
        }
        #pragma unroll
        for (int o = 16; o; o >>= 1) s += __shfl_xor_sync(0xFFFFFFFFu, s, o);
        if (!lane) ps[pi] = s + bps[p];
    }
    __syncthreads();

    int mya = ((lane >> 3) & 1) | (((lane >> 2) & 1) << 1)
            | (((lane >> 1) & 1) << 2) | ((lane & 1) << 3);
    float sc = 0.f;
    const float4* agg4 = (const float4*)agg;
    for (int pi = wid; pi < 64; pi += 8) {
        int p = p0 + pi;
        const float4* w4 = (const float4*)(wpf + p * CC);
        float part[16];
        #pragma unroll
        for (int a = 0; a < 16; a++) part[a] = 0.f;
        #pragma unroll
        for (int j = 0; j < 4; j++) {
            float4 wv = w4[lane + 32 * j];
            #pragma unroll
            for (int a = 0; a < 16; a++) {
                float4 av = agg4[a * 128 + lane + 32 * j];
                part[a] += av.x * wv.x + av.y * wv.y + av.z * wv.z + av.w * wv.w;
            }
        }
        float v16[16];
        #pragma unroll
        for (int a = 0; a < 16; a++)
            v16[a] = part[a] + __shfl_xor_sync(0xFFFFFFFFu, part[a], 16);
        float v8[8];
        #pragma unroll
        for (int i = 0; i < 8; i++) {
            float t = (lane & 8) ? v16[2 * i + 1] : v16[2 * i];
            v8[i] = t + __shfl_xor_sync(0xFFFFFFFFu, t, 8);
        }
        float v4[4];
        #pragma unroll
        for (int i = 0; i < 4; i++) {
            float t = (lane & 4) ? v8[2 * i + 1] : v8[2 * i];
            v4[i] = t + __shfl_xor_sync(0xFFFFFFFFu, t, 4);
        }
        float v2[2];
        #pragma unroll
        for (int i = 0; i < 2; i++) {
            float t = (lane & 2) ? v4[2 * i + 1] : v4[2 * i];
            v2[i] = t + __shfl_xor_sync(0xFFFFFFFFu, t, 2);
        }
        float t1 = (lane & 1) ? v2[1] : v2[0];
        float dot = t1 + __shfl_xor_sync(0xFFFFFFFFu, t1, 1);
        sc += watt[p] * tanhf(dot + bpf[p] + ps[pi]);
    }
    if (lane < 16) scw[wid][mya] = sc;
    __syncthreads();
    if (tid < 16) {
        float v = 0.f;
        #pragma unroll
        for (int j = 0; j < 8; j++) v += scw[j][tid];
        g_scorep[blockIdx.y][b * 16 + tid] = v;
    }
}

// ---------------------------------------------------------------------------
// softmax (redundant per block) + weighted sums.  grid (64,5), block 256
__global__ void k_final(float* __restrict__ out) {
    __shared__ float sc[16];
    __shared__ float aw[16];
    int b = blockIdx.x, tid = threadIdx.x;
    if (tid < 16) {
        float v = 0.f;
        #pragma unroll
        for (int j = 0; j < 8; j++) v += g_scorep[j][b * 16 + tid];
        sc[tid] = v;
    }
    __syncthreads();
    if (tid < 16) {
        float m = -1e30f;
        #pragma unroll
        for (int i = 0; i < 16; i++) m = fmaxf(m, sc[i]);
        float sum = 0.f;
        #pragma unroll
        for (int i = 0; i < 16; i++) sum += expf(sc[i] - m);
        aw[tid] = expf(sc[tid] - m) / sum;
    }
    __syncthreads();

    int hw = blockIdx.y * 256 + tid;
    if (hw < HWW) {
        const float* X = out + OFF_X + (size_t)b * AA * HWW;
        float s = 0.f;
        #pragma unroll
        for (int a = 0; a < 16; a++) s += X[a * HWW + hw] * aw[a];
        out[OFF_AX + b * HWW + hw] = s;
        out[OFF_Z + b * 1201 + 1 + hw] = s;
    }
    if (tid == 0 && blockIdx.y == 0) {
        float z = 0.f;
        #pragma unroll
        for (int a = 0; a < 16; a++) z += g_y[b * 16 + a] * aw[a];
        out[OFF_Z + b * 1201] = z;
    }
}

// ---------------------------------------------------------------------------
extern "C" void kernel_launch(void* const* d_in, const int* in_sizes, int n_in,
                              void* d_out, int out_size) {
    const float* enc  = (const float*)d_in[0];
    const float* feat = (const float*)d_in[1];
    const float* subj = (const float*)d_in[2];
    const float* w2   = (const float*)d_in[3];
    const float* b2   = (const float*)d_in[4];
    const float* w3   = (const float*)d_in[5];
    const float* b3   = (const float*)d_in[6];
    const float* wd1  = (const float*)d_in[7];
    const float* bd1  = (const float*)d_in[8];
    const float* wd2  = (const float*)d_in[9];
    const float* bd2  = (const float*)d_in[10];
    const float* wpf  = (const float*)d_in[11];
    const float* bpf  = (const float*)d_in[12];
    const float* wps  = (const float*)d_in[13];
    const float* bps  = (const float*)d_in[14];
    const float* watt = (const float*)d_in[15];
    float* out = (float*)d_out;

    cudaEventRecord(g_evFork, 0);
    cudaStreamWaitEvent(g_s1, g_evFork, 0);

    k_drt1f<<<dim3(64, 4), 384, 0, g_s1>>>(feat, wd1, 0);          // 1 (s1)
    k_drt1f<<<dim3(64, 4), 384, 0, g_s1>>>(feat, wd1, 4);          // 2 (s1)
    k_ydrt2<<<64, 512, 0, g_s1>>>(w2, b2, wd2, bd2, bd1, out);     // 3 (s1)
    k_x<<<dim3(64, 5), 128>>>(feat, w3, b3, out);                  // 4 (s0) <- profiled
    k_aggr<<<dim3(64, NZ), 256>>>(enc, out);                       // 5 (s0)
    k_score<<<dim3(64, 8), 256>>>(subj, wps, bps, wpf, bpf, watt); // 6 (s0)

    cudaEventRecord(g_evJoin, g_s1);
    cudaStreamWaitEvent(0, g_evJoin, 0);
    k_final<<<dim3(64, 5), 256>>>(out);                            // 7 (s0)
}

// round 9
// speedup vs baseline: 1.0858x; 1.0858x over previous
#include <cuda_runtime.h>
#include <math.h>

#define BB  64
#define AA  16
#define CC  512
#define HH  30
#define WW  40
#define HWW 1200
#define EE  256
#define PP  512

#define OFF_Z  0
#define OFF_MU 76864
#define OFF_S2 76928
#define OFF_AX 76992
#define OFF_X  153792

#define NZ 10

typedef unsigned long long ull;

#define FMA_F32X2(d, a, b, c) \
    asm("fma.rn.f32x2 %0, %1, %2, %3;" : "=l"(d) : "l"(a), "l"(b), "l"(c))
#define PACK_DUP_F32X2(out, v) \
    asm("mov.b64 %0, {%1, %1};" : "=l"(out) : "f"(v))
#define UNPACK_F32X2(lo, hi, in) \
    asm("mov.b64 {%0, %1}, %2;" : "=f"(lo), "=f"(hi) : "l"(in))

// scratch: every element written each launch before being read (no zeroing needed)
__device__ float g_mean[BB * CC];
__device__ float g_y[BB * AA];
__device__ float g_t1p[8][BB * 48];
__device__ float g_scorep[8][BB * AA];
__device__ float g_aggrp[NZ][BB * AA * CC];

// stream + events created once at library load (host-side resources only)
static cudaStream_t g_s1;
static cudaEvent_t g_evFork, g_evJoin;
namespace {
struct InitStreams {
    InitStreams() {
        cudaStreamCreateWithFlags(&g_s1, cudaStreamNonBlocking);
        cudaEventCreateWithFlags(&g_evFork, cudaEventDisableTiming);
        cudaEventCreateWithFlags(&g_evJoin, cudaEventDisableTiming);
    }
};
InitStreams g_initStreams;
}

// ---------------------------------------------------------------------------
// x[b,a,hw] = relu(w_sal3[a,:] . F[b,:,hw] + b_sal3[a])
// grid (128, 5), block 128: bx = b*2 + half, half -> a in [half*8, half*8+8).
// Thread computes 2 hw (t, t+128) x 8 a.  f32x2 accumulators over a-pairs.
__global__ void __launch_bounds__(128) k_x(const float* __restrict__ F,
                                           const float* __restrict__ w3,
                                           const float* __restrict__ b3,
                                           float* __restrict__ out) {
    __shared__ float ws[CC * 8];   // [c][a'] for this half -> natural a-pairs
    int b = blockIdx.x >> 1, half = blockIdx.x & 1;
    int tid = threadIdx.x;
    int a0 = half * 8;
    for (int i = tid; i < CC * 8; i += 128)
        ws[i] = w3[(a0 + (i & 7)) * CC + (i >> 3)];
    __syncthreads();

    int hw0 = blockIdx.y * 256 + tid;
    int hw1 = hw0 + 128;
    bool v0 = hw0 < HWW, v1 = hw1 < HWW;
    const float* Fb0 = F + (size_t)b * CC * HWW + (v0 ? hw0 : 0);
    const float* Fb1 = F + (size_t)b * CC * HWW + (v1 ? hw1 : 0);

    ull acc0[4], acc1[4];
    #pragma unroll
    for (int j = 0; j < 4; j++) { acc0[j] = 0ULL; acc1[j] = 0ULL; }

    #pragma unroll 8
    for (int c = 0; c < CC; c++) {
        float f0 = Fb0[c * HWW];
        float f1 = Fb1[c * HWW];
        ull f20, f21;
        PACK_DUP_F32X2(f20, f0);
        PACK_DUP_F32X2(f21, f1);
        const ulonglong2* wp = (const ulonglong2*)(ws + c * 8);
        ulonglong2 wA = wp[0];   // (a0,a1),(a2,a3)
        ulonglong2 wB = wp[1];   // (a4,a5),(a6,a7)
        FMA_F32X2(acc0[0], f20, wA.x, acc0[0]);
        FMA_F32X2(acc0[1], f20, wA.y, acc0[1]);
        FMA_F32X2(acc0[2], f20, wB.x, acc0[2]);
        FMA_F32X2(acc0[3], f20, wB.y, acc0[3]);
        FMA_F32X2(acc1[0], f21, wA.x, acc1[0]);
        FMA_F32X2(acc1[1], f21, wA.y, acc1[1]);
        FMA_F32X2(acc1[2], f21, wB.x, acc1[2]);
        FMA_F32X2(acc1[3], f21, wB.y, acc1[3]);
    }

    float* X = out + OFF_X + (size_t)b * AA * HWW;
    #pragma unroll
    for (int j = 0; j < 4; j++) {
        float lo0, hi0, lo1, hi1;
        UNPACK_F32X2(lo0, hi0, acc0[j]);
        UNPACK_F32X2(lo1, hi1, acc1[j]);
        int aL = a0 + 2 * j, aH = aL + 1;
        float ba = b3[aL], bb = b3[aH];
        if (v0) {
            X[aL * HWW + hw0] = fmaxf(lo0 + ba, 0.f);
            X[aH * HWW + hw0] = fmaxf(hi0 + bb, 0.f);
        }
        if (v1) {
            X[aL * HWW + hw1] = fmaxf(lo1 + ba, 0.f);
            X[aH * HWW + hw1] = fmaxf(hi1 + bb, 0.f);
        }
    }
}

// ---------------------------------------------------------------------------
// Fused drt1 conv partials + per-channel mean of F.
// grid (64, 4), block 384; yoff selects half of the 8 channel-chunks.
__global__ void __launch_bounds__(384) k_drt1f(const float* __restrict__ F,
                                               const float* __restrict__ w1,
                                               int yoff) {
    __shared__ float ch[2][HWW];
    __shared__ float wsh[64 * 49];
    __shared__ float csum[2][12];
    __shared__ float pos_acc[336];

    int chunkid = blockIdx.y + yoff;
    int b = blockIdx.x, c0 = chunkid * 64;
    int tid = threadIdx.x;
    int wid = tid >> 5, lane = tid & 31;

    for (int i = tid; i < 64 * 49; i += 384) wsh[i] = w1[c0 * 49 + i];

    int pos = tid / 7, kh = tid - pos * 7;
    bool active = tid < 336;
    int oh = pos >> 3, ow = pos & 7;
    int ih = oh * 5 - 2 + kh;
    int iw0 = ow * 5 - 2;
    bool ihok = active && ih >= 0;

    const float* Fb = F + ((size_t)b * CC + c0) * HWW;

    {
        float ps = 0.f;
        if (tid < 300) {
            float4 v = ((const float4*)Fb)[tid];
            ((float4*)ch[0])[tid] = v;
            ps = v.x + v.y + v.z + v.w;
        }
        #pragma unroll
        for (int o = 16; o; o >>= 1) ps += __shfl_xor_sync(0xFFFFFFFFu, ps, o);
        if (!lane) csum[0][wid] = ps;
    }
    __syncthreads();

    float acc = 0.f;
    for (int c = 0; c < 64; c++) {
        int cur = c & 1;
        if (c < 63) {
            float ps = 0.f;
            if (tid < 300) {
                float4 v = ((const float4*)(Fb + (size_t)(c + 1) * HWW))[tid];
                ((float4*)ch[cur ^ 1])[tid] = v;
                ps = v.x + v.y + v.z + v.w;
            }
            #pragma unroll
            for (int o = 16; o; o >>= 1) ps += __shfl_xor_sync(0xFFFFFFFFu, ps, o);
            if (!lane) csum[cur ^ 1][wid] = ps;
        }
        if (tid == 0) {
            float m = 0.f;
            #pragma unroll
            for (int w = 0; w < 12; w++) m += csum[cur][w];
            g_mean[b * CC + c0 + c] = m * (1.f / HWW);
        }
        if (ihok) {
            const float* row = ch[cur] + ih * WW;
            const float* wr = wsh + c * 49 + kh * 7;
            #pragma unroll
            for (int kw = 0; kw < 7; kw++) {
                int iw = iw0 + kw;
                if (iw >= 0) acc += row[iw] * wr[kw];
            }
        }
        __syncthreads();
    }

    if (active) pos_acc[tid] = acc;
    __syncthreads();
    if (active && kh == 0) {
        float s = pos_acc[tid] + pos_acc[tid + 1] + pos_acc[tid + 2]
                + pos_acc[tid + 3] + pos_acc[tid + 4] + pos_acc[tid + 5]
                + pos_acc[tid + 6];
        g_t1p[chunkid][b * 48 + pos] = s;
    }
}

// ---------------------------------------------------------------------------
// merged y + drt2.  grid 64, block 512
__global__ void __launch_bounds__(512) k_ydrt2(
    const float* __restrict__ w2, const float* __restrict__ b2,
    const float* __restrict__ wd2, const float* __restrict__ bd2,
    const float* __restrict__ bd1, float* __restrict__ out) {
    __shared__ float t1s[48];
    int b = blockIdx.x, tid = threadIdx.x;
    int a = tid >> 5, lane = tid & 31;

    if (tid < 48) {
        float t = 0.f;
        #pragma unroll
        for (int j = 0; j < 8; j++) t += g_t1p[j][b * 48 + tid];
        t1s[tid] = fmaxf(t + bd1[0], 0.f);
    }

    const float4* m4 = (const float4*)(g_mean + b * CC);
    const float4* w4 = (const float4*)(w2 + a * CC);
    float s = 0.f;
    #pragma unroll
    for (int i = 0; i < 4; i++) {
        float4 mv = m4[lane + 32 * i];
        float4 wv = w4[lane + 32 * i];
        s += mv.x * wv.x + mv.y * wv.y + mv.z * wv.z + mv.w * wv.w;
    }
    #pragma unroll
    for (int o = 16; o; o >>= 1) s += __shfl_xor_sync(0xFFFFFFFFu, s, o);
    if (!lane) g_y[b * AA + a] = s + b2[a];

    __syncthreads();
    if (tid < 64) {
        int o = tid >> 5;
        float s2 = 0.f;
        for (int i = lane; i < 48; i += 32) s2 += t1s[i] * wd2[o * 48 + i];
        #pragma unroll
        for (int sh = 16; sh; sh >>= 1) s2 += __shfl_xor_sync(0xFFFFFFFFu, s2, sh);
        if (!lane) {
            float v = s2 + bd2[o];
            if (o == 0) out[OFF_MU + b] = v;
            else        out[OFF_S2 + b] = expf(v);
        }
    }
}

// ---------------------------------------------------------------------------
// aggr partial v3 (scalar): grid (64, NZ), block 256.
#define ACH 20
__global__ void __launch_bounds__(256) k_aggr(const float* __restrict__ Eenc,
                                              const float* __restrict__ out) {
    __shared__ float Esh[ACH * 512];     // [k][c]
    __shared__ float Xsh[ACH * 16];      // [k][a]
    int b = blockIdx.x;
    int z = blockIdx.y;
    int tid = threadIdx.x;
    int tc = tid & 63;
    int ta = tid >> 6;

    const float* Eb = Eenc + (size_t)b * CC * HWW;
    const float* Xb = out + OFF_X + (size_t)b * AA * HWW;

    float acc[4][8];
    #pragma unroll
    for (int i = 0; i < 4; i++)
        #pragma unroll
        for (int j = 0; j < 8; j++) acc[i][j] = 0.f;

    int hwbase = z * 120;
    for (int chk = 0; chk < 6; chk++) {
        int k0 = hwbase + chk * ACH;
        #pragma unroll
        for (int r = 0; r < 2; r++) {
            int c = tid + r * 256;
            const float4* Er = (const float4*)(Eb + (size_t)c * HWW + k0);
            #pragma unroll
            for (int q = 0; q < 5; q++) {
                float4 v = Er[q];
                Esh[(q * 4 + 0) * 512 + c] = v.x;
                Esh[(q * 4 + 1) * 512 + c] = v.y;
                Esh[(q * 4 + 2) * 512 + c] = v.z;
                Esh[(q * 4 + 3) * 512 + c] = v.w;
            }
        }
        if (tid < 80) {
            int aa = tid / 5, q = tid % 5;
            float4 v = *(const float4*)(Xb + aa * HWW + k0 + q * 4);
            Xsh[(q * 4 + 0) * 16 + aa] = v.x;
            Xsh[(q * 4 + 1) * 16 + aa] = v.y;
            Xsh[(q * 4 + 2) * 16 + aa] = v.z;
            Xsh[(q * 4 + 3) * 16 + aa] = v.w;
        }
        __syncthreads();
        #pragma unroll
        for (int k = 0; k < ACH; k++) {
            float4 e0 = *(const float4*)(Esh + k * 512 + tc * 4);
            float4 e1 = *(const float4*)(Esh + k * 512 + 256 + tc * 4);
            float4 xv = *(const float4*)(Xsh + k * 16 + ta * 4);
            float ev[8] = {e0.x, e0.y, e0.z, e0.w, e1.x, e1.y, e1.z, e1.w};
            float xa[4] = {xv.x, xv.y, xv.z, xv.w};
            #pragma unroll
            for (int i = 0; i < 4; i++)
                #pragma unroll
                for (int j = 0; j < 8; j++)
                    acc[i][j] += xa[i] * ev[j];
        }
        __syncthreads();
    }

    float* dst = g_aggrp[z] + (size_t)b * AA * CC;
    #pragma unroll
    for (int i = 0; i < 4; i++) {
        int a = ta * 4 + i;
        float4 s0, s1;
        s0.x = acc[i][0] * (1.f / HWW); s0.y = acc[i][1] * (1.f / HWW);
        s0.z = acc[i][2] * (1.f / HWW); s0.w = acc[i][3] * (1.f / HWW);
        s1.x = acc[i][4] * (1.f / HWW); s1.y = acc[i][5] * (1.f / HWW);
        s1.z = acc[i][6] * (1.f / HWW); s1.w = acc[i][7] * (1.f / HWW);
        *(float4*)(dst + a * CC + tc * 4) = s0;
        *(float4*)(dst + a * CC + 256 + tc * 4) = s1;
    }
}

// ---------------------------------------------------------------------------
// partial attention scores: grid (64, 8), block 256, 64 p's per block
__global__ void __launch_bounds__(256) k_score(
    const float* __restrict__ subj, const float* __restrict__ wps,
    const float* __restrict__ bps, const float* __restrict__ wpf,
    const float* __restrict__ bpf, const float* __restrict__ watt) {
    __shared__ float ssub[EE];
    __shared__ float ps[64];
    __shared__ float agg[AA * CC];
    __shared__ float scw[8][16];
    int b = blockIdx.x, p0 = blockIdx.y * 64;
    int tid = threadIdx.x;
    int wid = tid >> 5, lane = tid & 31;

    for (int i = tid; i < EE; i += 256) ssub[i] = subj[b * EE + i];
    for (int i = tid; i < AA * CC; i += 256) {
        float v = 0.f;
        #pragma unroll
        for (int z = 0; z < NZ; z++) v += g_aggrp[z][(size_t)b * AA * CC + i];
        agg[i] = v;
    }
    __syncthreads();

    for (int pi = wid; pi < 64; pi += 8) {
        int p = p0 + pi;
        const float4* w4 = (const float4*)(wps + p * EE);
        const float4* s4 = (const float4*)ssub;
        float s = 0.f;
        #pragma unroll
        for (int i = 0; i < 2; i++) {
            float4 wv = w4[lane + 32 * i], sv = s4[lane + 32 * i];
            s += wv.x * sv.x + wv.y * sv.y + wv.z * sv.z + wv.w * sv.w;
        }
        #pragma unroll
        for (int o = 16; o; o >>= 1) s += __shfl_xor_sync(0xFFFFFFFFu, s, o);
        if (!lane) ps[pi] = s + bps[p];
    }
    __syncthreads();

    int mya = ((lane >> 3) & 1) | (((lane >> 2) & 1) << 1)
            | (((lane >> 1) & 1) << 2) | ((lane & 1) << 3);
    float sc = 0.f;
    const float4* agg4 = (const float4*)agg;
    for (int pi = wid; pi < 64; pi += 8) {
        int p = p0 + pi;
        const float4* w4 = (const float4*)(wpf + p * CC);
        float part[16];
        #pragma unroll
        for (int a = 0; a < 16; a++) part[a] = 0.f;
        #pragma unroll
        for (int j = 0; j < 4; j++) {
            float4 wv = w4[lane + 32 * j];
            #pragma unroll
            for (int a = 0; a < 16; a++) {
                float4 av = agg4[a * 128 + lane + 32 * j];
                part[a] += av.x * wv.x + av.y * wv.y + av.z * wv.z + av.w * wv.w;
            }
        }
        float v16[16];
        #pragma unroll
        for (int a = 0; a < 16; a++)
            v16[a] = part[a] + __shfl_xor_sync(0xFFFFFFFFu, part[a], 16);
        float v8[8];
        #pragma unroll
        for (int i = 0; i < 8; i++) {
            float t = (lane & 8) ? v16[2 * i + 1] : v16[2 * i];
            v8[i] = t + __shfl_xor_sync(0xFFFFFFFFu, t, 8);
        }
        float v4[4];
        #pragma unroll
        for (int i = 0; i < 4; i++) {
            float t = (lane & 4) ? v8[2 * i + 1] : v8[2 * i];
            v4[i] = t + __shfl_xor_sync(0xFFFFFFFFu, t, 4);
        }
        float v2[2];
        #pragma unroll
        for (int i = 0; i < 2; i++) {
            float t = (lane & 2) ? v4[2 * i + 1] : v4[2 * i];
            v2[i] = t + __shfl_xor_sync(0xFFFFFFFFu, t, 2);
        }
        float t1 = (lane & 1) ? v2[1] : v2[0];
        float dot = t1 + __shfl_xor_sync(0xFFFFFFFFu, t1, 1);
        sc += watt[p] * tanhf(dot + bpf[p] + ps[pi]);
    }
    if (lane < 16) scw[wid][mya] = sc;
    __syncthreads();
    if (tid < 16) {
        float v = 0.f;
        #pragma unroll
        for (int j = 0; j < 8; j++) v += scw[j][tid];
        g_scorep[blockIdx.y][b * 16 + tid] = v;
    }
}

// ---------------------------------------------------------------------------
// softmax (redundant per block) + weighted sums.  grid (64,5), block 256
__global__ void k_final(float* __restrict__ out) {
    __shared__ float sc[16];
    __shared__ float aw[16];
    int b = blockIdx.x, tid = threadIdx.x;
    if (tid < 16) {
        float v = 0.f;
        #pragma unroll
        for (int j = 0; j < 8; j++) v += g_scorep[j][b * 16 + tid];
        sc[tid] = v;
    }
    __syncthreads();
    if (tid < 16) {
        float m = -1e30f;
        #pragma unroll
        for (int i = 0; i < 16; i++) m = fmaxf(m, sc[i]);
        float sum = 0.f;
        #pragma unroll
        for (int i = 0; i < 16; i++) sum += expf(sc[i] - m);
        aw[tid] = expf(sc[tid] - m) / sum;
    }
    __syncthreads();

    int hw = blockIdx.y * 256 + tid;
    if (hw < HWW) {
        const float* X = out + OFF_X + (size_t)b * AA * HWW;
        float s = 0.f;
        #pragma unroll
        for (int a = 0; a < 16; a++) s += X[a * HWW + hw] * aw[a];
        out[OFF_AX + b * HWW + hw] = s;
        out[OFF_Z + b * 1201 + 1 + hw] = s;
    }
    if (tid == 0 && blockIdx.y == 0) {
        float z = 0.f;
        #pragma unroll
        for (int a = 0; a < 16; a++) z += g_y[b * 16 + a] * aw[a];
        out[OFF_Z + b * 1201] = z;
    }
}

// ---------------------------------------------------------------------------
extern "C" void kernel_launch(void* const* d_in, const int* in_sizes, int n_in,
                              void* d_out, int out_size) {
    const float* enc  = (const float*)d_in[0];
    const float* feat = (const float*)d_in[1];
    const float* subj = (const float*)d_in[2];
    const float* w2   = (const float*)d_in[3];
    const float* b2   = (const float*)d_in[4];
    const float* w3   = (const float*)d_in[5];
    const float* b3   = (const float*)d_in[6];
    const float* wd1  = (const float*)d_in[7];
    const float* bd1  = (const float*)d_in[8];
    const float* wd2  = (const float*)d_in[9];
    const float* bd2  = (const float*)d_in[10];
    const float* wpf  = (const float*)d_in[11];
    const float* bpf  = (const float*)d_in[12];
    const float* wps  = (const float*)d_in[13];
    const float* bps  = (const float*)d_in[14];
    const float* watt = (const float*)d_in[15];
    float* out = (float*)d_out;

    cudaEventRecord(g_evFork, 0);
    cudaStreamWaitEvent(g_s1, g_evFork, 0);

    k_drt1f<<<dim3(64, 4), 384, 0, g_s1>>>(feat, wd1, 0);          // 1 (s1)
    k_drt1f<<<dim3(64, 4), 384, 0, g_s1>>>(feat, wd1, 4);          // 2 (s1)
    k_ydrt2<<<64, 512, 0, g_s1>>>(w2, b2, wd2, bd2, bd1, out);     // 3 (s1)
    k_x<<<dim3(128, 5), 128>>>(feat, w3, b3, out);                 // 4 (s0) <- profiled
    k_aggr<<<dim3(64, NZ), 256>>>(enc, out);                       // 5 (s0)
    k_score<<<dim3(64, 8), 256>>>(subj, wps, bps, wpf, bpf, watt); // 6 (s0)

    cudaEventRecord(g_evJoin, g_s1);
    cudaStreamWaitEvent(0, g_evJoin, 0);
    k_final<<<dim3(64, 5), 256>>>(out);                            // 7 (s0)
}